// round 7
// baseline (speedup 1.0000x reference)
#include <cuda_runtime.h>
#include <cuda_bf16.h>
#include <cstdint>

#define H            128
#define BASKET_LEN   200
#define NT           1024          // 32 warps per block
#define WARPS        32
#define GATHER_BLKS  7             // 7*32 = 224 warps >= 200 items
#define NB           (GATHER_BLKS + 1)   // +1 block for gh matvec

// Scratch (device globals; no allocation). All slots rewritten every launch.
__device__ float        g_part[GATHER_BLKS][H];
__device__ float        g_gh[3 * H];
__device__ unsigned int g_ticket;   // zero at load; reset by tail each launch

__device__ __forceinline__ float fast_sigmoid(float x) {
    return __fdividef(1.0f, 1.0f + __expf(-x));
}
__device__ __forceinline__ float fast_tanh(float x) {
    const float t = __expf(-2.0f * x);
    return __fdividef(1.0f - t, 1.0f + t);
}

__global__ __launch_bounds__(NT, 1)
void encoder_rnn_fused(const int* __restrict__ basket,
                       const float* __restrict__ hidden,
                       const float* __restrict__ emb_table,
                       const float* __restrict__ w_ih,
                       const float* __restrict__ w_hh,
                       const float* __restrict__ b_ih,
                       const float* __restrict__ b_hh,
                       float* __restrict__ out,
                       int out_size)
{
    __shared__ float s_red[WARPS * H];      // 16 KB: gather per-warp rows
    __shared__ float s_emb[H];
    __shared__ float s_gi[3 * H];
    __shared__ float s_h[H];
    __shared__ unsigned s_last;

    const int tid  = threadIdx.x;
    const int lane = tid & 31;
    const int w    = tid >> 5;
    const int blk  = blockIdx.x;

    if (blk < GATHER_BLKS) {
        // ---- Phase A: one warp per basket item, full 512B row per LDG.128 ----
        const int item = blk * WARPS + w;
        float4 v = make_float4(0.f, 0.f, 0.f, 0.f);
        if (item < BASKET_LEN) {
            const long idx = (long)__ldg(&basket[item]);   // uniform: LDG broadcast
            v = __ldg(&reinterpret_cast<const float4*>(emb_table)[idx * 32 + lane]);
        }
        reinterpret_cast<float4*>(s_red)[w * 32 + lane] = v;
        __syncthreads();
        if (tid < H) {
            // 4 accumulators: break the 32-deep serial FADD chain
            float a0 = 0.f, a1 = 0.f, a2 = 0.f, a3 = 0.f;
            #pragma unroll
            for (int ww = 0; ww < WARPS; ww += 4) {
                a0 += s_red[(ww + 0) * H + tid];
                a1 += s_red[(ww + 1) * H + tid];
                a2 += s_red[(ww + 2) * H + tid];
                a3 += s_red[(ww + 3) * H + tid];
            }
            g_part[blk][tid] = (a0 + a1) + (a2 + a3);
        }
    } else {
        // ---- Phase A': gh = w_hh @ h + b_hh (independent of gather) ----
        const float4 h4 = __ldg(&reinterpret_cast<const float4*>(hidden)[lane]);
        const int r0 = w * 12;                       // 32 warps * 12 rows = 384
        float p[12];
        #pragma unroll
        for (int j = 0; j < 12; j++) {
            const float4 a = __ldg(&reinterpret_cast<const float4*>(w_hh)[(size_t)(r0 + j) * 32 + lane]);
            p[j] = a.x * h4.x + a.y * h4.y + a.z * h4.z + a.w * h4.w;
        }
        #pragma unroll
        for (int off = 16; off; off >>= 1)
            #pragma unroll
            for (int j = 0; j < 12; j++)
                p[j] += __shfl_xor_sync(0xFFFFFFFFu, p[j], off);
        #pragma unroll
        for (int j = 0; j < 12; j++)
            if (lane == j) g_gh[r0 + j] = p[j] + __ldg(&b_hh[r0 + j]);
    }

    // ---- Ticket: single acq_rel atomic (release prior STG, acquire peers') ----
    __syncthreads();
    if (tid == 0) {
        unsigned old;
        asm volatile("atom.acq_rel.gpu.global.add.u32 %0, [%1], 1;"
                     : "=r"(old) : "l"(&g_ticket) : "memory");
        s_last = (old == NB - 1);
    }
    __syncthreads();
    if (!s_last) return;

    // ---- Phase B: reduce partials -> emb; load h ----
    if (tid < H) {
        float a0 = g_part[0][tid] + g_part[1][tid];
        float a1 = g_part[2][tid] + g_part[3][tid];
        float a2 = g_part[4][tid] + g_part[5][tid];
        float a3 = g_part[6][tid];
        s_emb[tid] = ((a0 + a1) + (a2 + a3)) * (1.0f / (float)H);
        s_h[tid]   = __ldg(&hidden[tid]);
    }
    __syncthreads();

    // ---- Phase C: gi = w_ih @ emb + b_ih (32 warps x 12 rows) ----
    {
        const float4 e4 = reinterpret_cast<const float4*>(s_emb)[lane];
        const int r0 = w * 12;
        float p[12];
        #pragma unroll
        for (int j = 0; j < 12; j++) {
            const float4 a = __ldg(&reinterpret_cast<const float4*>(w_ih)[(size_t)(r0 + j) * 32 + lane]);
            p[j] = a.x * e4.x + a.y * e4.y + a.z * e4.z + a.w * e4.w;
        }
        #pragma unroll
        for (int off = 16; off; off >>= 1)
            #pragma unroll
            for (int j = 0; j < 12; j++)
                p[j] += __shfl_xor_sync(0xFFFFFFFFu, p[j], off);
        #pragma unroll
        for (int j = 0; j < 12; j++)
            if (lane == j) s_gi[r0 + j] = p[j] + __ldg(&b_ih[r0 + j]);
    }
    __syncthreads();

    // ---- Phase D: GRU gates + replicated output ----
    if (tid < H) {
        const float i_r = s_gi[tid];
        const float i_z = s_gi[H + tid];
        const float i_n = s_gi[2 * H + tid];
        const float h_r = g_gh[tid];
        const float h_z = g_gh[H + tid];
        const float h_n = g_gh[2 * H + tid];

        const float r = fast_sigmoid(i_r + h_r);
        const float z = fast_sigmoid(i_z + h_z);
        const float n = fast_tanh(i_n + r * h_n);
        const float h_new = (1.0f - z) * n + z * s_h[tid];

        for (int o = tid; o < out_size; o += H)
            out[o] = h_new;
    }

    if (tid == 0) g_ticket = 0;   // reset for next graph replay
}

extern "C" void kernel_launch(void* const* d_in, const int* in_sizes, int n_in,
                              void* d_out, int out_size)
{
    const int*   basket    = (const int*)  d_in[0];
    const float* hidden    = (const float*)d_in[1];
    const float* emb_table = (const float*)d_in[2];
    const float* w_ih      = (const float*)d_in[3];
    const float* w_hh      = (const float*)d_in[4];
    const float* b_ih      = (const float*)d_in[5];
    const float* b_hh      = (const float*)d_in[6];
    float* out = (float*)d_out;

    encoder_rnn_fused<<<NB, NT>>>(basket, hidden, emb_table,
                                  w_ih, w_hh, b_ih, b_hh,
                                  out, out_size);
}